// round 9
// baseline (speedup 1.0000x reference)
#include <cuda_runtime.h>

// Idx2PixelLayer bilinear gather — two-pass (image-half) + predicated 4-points
// per lane-group. Pass p gathers only points whose i0 is in half p; expected
// 2 of 4 points active -> expected 4 gather LDG.128 in flight per thread
// (matches single-pass R4 density) while the per-pass gather line-footprint
// (~0.5M L2 tags) fits L2, converting ~37% sector-repeats into hits.

#define HW 2048
#define CCH 8

__device__ __forceinline__ float4 ldg_stream4(const float* p) {
    float4 v;
    asm volatile("ld.global.cs.v4.f32 {%0,%1,%2,%3}, [%4];"
                 : "=f"(v.x), "=f"(v.y), "=f"(v.z), "=f"(v.w) : "l"(p));
    return v;
}

__device__ __forceinline__ void stg_stream4(float* p, float4 v) {
    asm volatile("st.global.cs.v4.f32 [%0], {%1,%2,%3,%4};"
                 :: "l"(p), "f"(v.x), "f"(v.y), "f"(v.z), "f"(v.w) : "memory");
}

__global__ __launch_bounds__(256) void idx2pixel_2p4_kernel(
    const float* __restrict__ coords,
    const float* __restrict__ vis,
    float* __restrict__ out,
    int n, int pass)
{
    int gtid  = blockIdx.x * blockDim.x + threadIdx.x;
    int w     = gtid >> 5;            // global warp id
    int lane  = threadIdx.x & 31;
    int group = lane >> 2;            // 0..7
    int j     = lane & 3;             // 0..3 within group
    int pbase = (w * 8 + group) * 4;  // first of 4 points
    if (pbase >= n) return;

    unsigned mask = __activemask();
    const float M = (float)(HW - 4);   // 2044

    // 4 points' coords: (x0,y0,x1,y1) (x2,y2,x3,y3)
    float4 cA = ldg_stream4(coords + (size_t)pbase * 2);
    float4 cB = ldg_stream4(coords + (size_t)pbase * 2 + 4);

    float cx[4] = {cA.x, cA.z, cB.x, cB.z};
    float cy[4] = {cA.y, cA.w, cB.y, cB.w};

    float d0[4], d1[4];
    int   off[4];
    bool  act[4];

    #pragma unroll
    for (int k = 0; k < 4; k++) {
        float c0 = fmodf(cx[k] - 1.0f, M); if (c0 < 0.0f) c0 += M; c0 += 1.0f;
        float c1 = fmodf(cy[k] - 1.0f, M); if (c1 < 0.0f) c1 += M; c1 += 1.0f;
        float f0 = floorf(c0), f1 = floorf(c1);
        d0[k] = c0 - f0;  d1[k] = c1 - f1;
        int i0 = (int)f0, i1 = (int)f1;
        off[k] = (i0 * HW + i1) * CCH + j * 4;
        act[k] = ((i0 >> 10) == pass) && (pbase + k < n);
    }

    // ---- predicated gathers: expected 4 in flight per thread ----
    float4 Av[4], Bv[4];
    #pragma unroll
    for (int k = 0; k < 4; k++) {
        Av[k] = make_float4(0.f, 0.f, 0.f, 0.f);
        Bv[k] = Av[k];
        if (act[k]) {
            const float* p = vis + off[k];
            Av[k] = __ldg(reinterpret_cast<const float4*>(p));               // row i0  (tl|bl half)
            Bv[k] = __ldg(reinterpret_cast<const float4*>(p + HW * CCH));    // row i0+1 (tr|br half)
        }
    }

    #pragma unroll
    for (int k = 0; k < 4; k++) {
        // lanes 0,1 -> mt = tr + d0*(tl-tr); lanes 2,3 -> mb = br + d0*(bl-br)
        float4 v;
        v.x = Bv[k].x + d0[k] * (Av[k].x - Bv[k].x);
        v.y = Bv[k].y + d0[k] * (Av[k].y - Bv[k].y);
        v.z = Bv[k].z + d0[k] * (Av[k].z - Bv[k].z);
        v.w = Bv[k].w + d0[k] * (Av[k].w - Bv[k].w);

        float4 o;
        o.x = __shfl_xor_sync(mask, v.x, 2);
        o.y = __shfl_xor_sync(mask, v.y, 2);
        o.z = __shfl_xor_sync(mask, v.z, 2);
        o.w = __shfl_xor_sync(mask, v.w, 2);

        float4 mt, mb;
        if (j < 2) { mt = v; mb = o; } else { mt = o; mb = v; }

        float4 r;
        r.x = mb.x + d1[k] * (mt.x - mb.x);
        r.y = mb.y + d1[k] * (mt.y - mb.y);
        r.z = mb.z + d1[k] * (mt.z - mb.z);
        r.w = mb.w + d1[k] * (mt.w - mb.w);

        // off = c > 2048 never true (c in [1, 2045)): no zeroing.
        if (act[k] && j < 2)
            stg_stream4(out + ((size_t)(pbase + k) * CCH) + j * 4, r);
    }
}

extern "C" void kernel_launch(void* const* d_in, const int* in_sizes, int n_in,
                              void* d_out, int out_size)
{
    const float* coords = (const float*)d_in[0];
    const float* vis    = (const float*)d_in[1];
    float* out          = (float*)d_out;

    int n = in_sizes[0] / 2;             // number of points
    int threads = 256;                    // 8 warps * 8 groups * 4 = 256 points/block
    int ppb = (threads / 32) * 8 * 4;
    int blocks = (n + ppb - 1) / ppb;
    idx2pixel_2p4_kernel<<<blocks, threads>>>(coords, vis, out, n, 0);
    idx2pixel_2p4_kernel<<<blocks, threads>>>(coords, vis, out, n, 1);
}

// round 10
// speedup vs baseline: 1.1238x; 1.1238x over previous
#include <cuda_runtime.h>

// Idx2PixelLayer bilinear gather — deterministic compaction two-phase.
//  P0 scatter: coord math once per point; record {d0,d1,(i0<<11)|i1,pid} into
//     the image-half list, block-private chunk (ballot + warp-prefix ranks;
//     no atomics, per-block counts fully rewritten each replay -> no zeroing).
//  P1/P2: dense processing of each half-list with the R4 winner execution
//     shape (4 lanes/point, 2 records/lane-group, 4 gather LDG.128 in flight).
//     Per-pass gather footprint ~0.43M L2 lines < ~1M tags -> sector repeats
//     (~37% of gather traffic) become L2 hits.

#define HW   2048
#define CCH  8
#define NMAX (2 * 1024 * 1024)       // max points supported by compaction path
#define MAXB (NMAX / 256)            // max scatter blocks

__device__ float4 g_rec[2][NMAX];    // per-half records, chunked by block
__device__ int    g_bcnt[2][MAXB];   // per-block per-half counts

__device__ __forceinline__ float2 ldg_cs2(const float* p) {
    float2 v;
    asm volatile("ld.global.cs.v2.f32 {%0,%1}, [%2];"
                 : "=f"(v.x), "=f"(v.y) : "l"(p));
    return v;
}
__device__ __forceinline__ void stg_cs4(float* p, float4 v) {
    asm volatile("st.global.cs.v4.f32 [%0], {%1,%2,%3,%4};"
                 :: "l"(p), "f"(v.x), "f"(v.y), "f"(v.z), "f"(v.w) : "memory");
}

// ---------------- P0: scatter ----------------
__global__ __launch_bounds__(256) void scatter_kernel(
    const float* __restrict__ coords, int n)
{
    int tid = threadIdx.x;
    int bid = blockIdx.x;
    int t   = bid * 256 + tid;
    bool active = t < n;

    float2 xy = make_float2(1.0f, 1.0f);
    if (active) xy = ldg_cs2(coords + (size_t)t * 2);

    const float M = (float)(HW - 4);   // 2044
    float c0 = fmodf(xy.x - 1.0f, M); if (c0 < 0.0f) c0 += M; c0 += 1.0f;
    float c1 = fmodf(xy.y - 1.0f, M); if (c1 < 0.0f) c1 += M; c1 += 1.0f;
    float f0 = floorf(c0), f1 = floorf(c1);
    float d0 = c0 - f0,   d1 = c1 - f1;
    int   i0 = (int)f0,   i1 = (int)f1;
    int   h  = (i0 >> 10) & 1;         // image half (i0 in [1,2044])

    int w    = tid >> 5;
    int lane = tid & 31;
    unsigned b0 = __ballot_sync(0xffffffffu, active && h == 0);
    unsigned b1 = __ballot_sync(0xffffffffu, active && h == 1);

    __shared__ int wcnt[2][8];
    if (lane == 0) { wcnt[0][w] = __popc(b0); wcnt[1][w] = __popc(b1); }
    __syncthreads();

    int pre0 = 0, pre1 = 0, tot0 = 0, tot1 = 0;
    #pragma unroll
    for (int i = 0; i < 8; i++) {
        int a = wcnt[0][i], b = wcnt[1][i];
        if (i < w) { pre0 += a; pre1 += b; }
        tot0 += a; tot1 += b;
    }

    if (active) {
        unsigned lm = (1u << lane) - 1u;
        int rank = (h == 0) ? (pre0 + __popc(b0 & lm))
                            : (pre1 + __popc(b1 & lm));
        float4 rec;
        rec.x = d0;
        rec.y = d1;
        rec.z = __int_as_float((i0 << 11) | i1);
        rec.w = __int_as_float(t);
        g_rec[h][(size_t)bid * 256 + rank] = rec;
    }
    if (tid == 0) { g_bcnt[0][bid] = tot0; g_bcnt[1][bid] = tot1; }
}

// ---------------- P1/P2: dense per-half processing ----------------
__global__ __launch_bounds__(256) void process_kernel(
    const float* __restrict__ vis,
    float* __restrict__ out,
    int pass)
{
    int bid   = blockIdx.x;
    int cnt   = g_bcnt[pass][bid];
    const float4* recs = g_rec[pass] + (size_t)bid * 256;

    int lane  = threadIdx.x & 31;
    int w     = threadIdx.x >> 5;
    int group = lane >> 2;
    int j     = lane & 3;
    int gidx  = w * 8 + group;        // 0..63

    for (int base = 0; base < cnt; base += 128) {
        int  e0   = base + gidx * 2;
        int  e1   = e0 + 1;
        bool actA = e0 < cnt;
        bool actB = e1 < cnt;

        float4 ra = make_float4(0.f, 0.f, 0.f, 0.f), rb = ra;
        if (actA) ra = recs[e0];
        if (actB) rb = recs[e1];

        float d0a = ra.x, d1a = ra.y;
        float d0b = rb.x, d1b = rb.y;
        int pka = __float_as_int(ra.z), pida = __float_as_int(ra.w);
        int pkb = __float_as_int(rb.z), pidb = __float_as_int(rb.w);
        int offa = ((pka >> 11) * HW + (pka & 2047)) * CCH + j * 4;
        int offb = ((pkb >> 11) * HW + (pkb & 2047)) * CCH + j * 4;

        float4 Aa = make_float4(0.f, 0.f, 0.f, 0.f), Ba = Aa, Ab = Aa, Bb = Aa;
        if (actA) {
            Aa = __ldg(reinterpret_cast<const float4*>(vis + offa));            // row i0  (tl|bl)
            Ba = __ldg(reinterpret_cast<const float4*>(vis + offa + HW * CCH)); // row i0+1 (tr|br)
        }
        if (actB) {
            Ab = __ldg(reinterpret_cast<const float4*>(vis + offb));
            Bb = __ldg(reinterpret_cast<const float4*>(vis + offb + HW * CCH));
        }

        // lanes 0,1 -> mt = tr + d0*(tl-tr); lanes 2,3 -> mb = br + d0*(bl-br)
        float4 va, vb;
        va.x = Ba.x + d0a * (Aa.x - Ba.x);
        va.y = Ba.y + d0a * (Aa.y - Ba.y);
        va.z = Ba.z + d0a * (Aa.z - Ba.z);
        va.w = Ba.w + d0a * (Aa.w - Ba.w);
        vb.x = Bb.x + d0b * (Ab.x - Bb.x);
        vb.y = Bb.y + d0b * (Ab.y - Bb.y);
        vb.z = Bb.z + d0b * (Ab.z - Bb.z);
        vb.w = Bb.w + d0b * (Ab.w - Bb.w);

        float4 oa, ob;
        oa.x = __shfl_xor_sync(0xffffffffu, va.x, 2);
        oa.y = __shfl_xor_sync(0xffffffffu, va.y, 2);
        oa.z = __shfl_xor_sync(0xffffffffu, va.z, 2);
        oa.w = __shfl_xor_sync(0xffffffffu, va.w, 2);
        ob.x = __shfl_xor_sync(0xffffffffu, vb.x, 2);
        ob.y = __shfl_xor_sync(0xffffffffu, vb.y, 2);
        ob.z = __shfl_xor_sync(0xffffffffu, vb.z, 2);
        ob.w = __shfl_xor_sync(0xffffffffu, vb.w, 2);

        float4 mta, mba, mtb, mbb;
        if (j < 2) { mta = va; mba = oa; mtb = vb; mbb = ob; }
        else       { mta = oa; mba = va; mtb = ob; mbb = vb; }

        float4 qa, qb;
        qa.x = mba.x + d1a * (mta.x - mba.x);
        qa.y = mba.y + d1a * (mta.y - mba.y);
        qa.z = mba.z + d1a * (mta.z - mba.z);
        qa.w = mba.w + d1a * (mta.w - mba.w);
        qb.x = mbb.x + d1b * (mtb.x - mbb.x);
        qb.y = mbb.y + d1b * (mtb.y - mbb.y);
        qb.z = mbb.z + d1b * (mtb.z - mbb.z);
        qb.w = mbb.w + d1b * (mtb.w - mbb.w);

        // off = c > 2048 never true (c in [1, 2045)): no zeroing.
        if (j < 2) {
            if (actA) stg_cs4(out + (size_t)pida * CCH + j * 4, qa);
            if (actB) stg_cs4(out + (size_t)pidb * CCH + j * 4, qb);
        }
    }
}

// ---------------- fallback: R4 single-pass (n > NMAX) ----------------
__global__ __launch_bounds__(256) void idx2pixel_r4_kernel(
    const float* __restrict__ coords,
    const float* __restrict__ vis,
    float* __restrict__ out,
    int n)
{
    int gtid  = blockIdx.x * blockDim.x + threadIdx.x;
    int w     = gtid >> 5;
    int lane  = threadIdx.x & 31;
    int group = lane >> 2;
    int j     = lane & 3;
    int pbase = (w * 8 + group) * 2;
    if (pbase >= n) return;

    unsigned mask = __activemask();
    const float M = (float)(HW - 4);
    float4 cxy;
    cxy.x = coords[(size_t)pbase * 2 + 0];
    cxy.y = coords[(size_t)pbase * 2 + 1];
    cxy.z = (pbase + 1 < n) ? coords[(size_t)pbase * 2 + 2] : 1.0f;
    cxy.w = (pbase + 1 < n) ? coords[(size_t)pbase * 2 + 3] : 1.0f;

    float c0a = fmodf(cxy.x - 1.0f, M); if (c0a < 0.0f) c0a += M; c0a += 1.0f;
    float c1a = fmodf(cxy.y - 1.0f, M); if (c1a < 0.0f) c1a += M; c1a += 1.0f;
    float c0b = fmodf(cxy.z - 1.0f, M); if (c0b < 0.0f) c0b += M; c0b += 1.0f;
    float c1b = fmodf(cxy.w - 1.0f, M); if (c1b < 0.0f) c1b += M; c1b += 1.0f;
    float f0a = floorf(c0a), f1a = floorf(c1a);
    float f0b = floorf(c0b), f1b = floorf(c1b);
    float d0a = c0a - f0a, d1a = c1a - f1a;
    float d0b = c0b - f0b, d1b = c1b - f1b;
    int i0a = (int)f0a, i1a = (int)f1a;
    int i0b = (int)f0b, i1b = (int)f1b;

    const float* pa0 = vis + ((size_t)i0a * HW + i1a) * CCH + j * 4;
    const float* pb0 = vis + ((size_t)i0b * HW + i1b) * CCH + j * 4;
    float4 Aa = __ldg(reinterpret_cast<const float4*>(pa0));
    float4 Ba = __ldg(reinterpret_cast<const float4*>(pa0 + HW * CCH));
    float4 Ab = __ldg(reinterpret_cast<const float4*>(pb0));
    float4 Bb = __ldg(reinterpret_cast<const float4*>(pb0 + HW * CCH));

    float4 va, vb;
    va.x = Ba.x + d0a * (Aa.x - Ba.x); va.y = Ba.y + d0a * (Aa.y - Ba.y);
    va.z = Ba.z + d0a * (Aa.z - Ba.z); va.w = Ba.w + d0a * (Aa.w - Ba.w);
    vb.x = Bb.x + d0b * (Ab.x - Bb.x); vb.y = Bb.y + d0b * (Ab.y - Bb.y);
    vb.z = Bb.z + d0b * (Ab.z - Bb.z); vb.w = Bb.w + d0b * (Ab.w - Bb.w);

    float4 oa, ob;
    oa.x = __shfl_xor_sync(mask, va.x, 2); oa.y = __shfl_xor_sync(mask, va.y, 2);
    oa.z = __shfl_xor_sync(mask, va.z, 2); oa.w = __shfl_xor_sync(mask, va.w, 2);
    ob.x = __shfl_xor_sync(mask, vb.x, 2); ob.y = __shfl_xor_sync(mask, vb.y, 2);
    ob.z = __shfl_xor_sync(mask, vb.z, 2); ob.w = __shfl_xor_sync(mask, vb.w, 2);

    float4 mta, mba, mtb, mbb;
    if (j < 2) { mta = va; mba = oa; mtb = vb; mbb = ob; }
    else       { mta = oa; mba = va; mtb = ob; mbb = vb; }

    float4 qa, qb;
    qa.x = mba.x + d1a * (mta.x - mba.x); qa.y = mba.y + d1a * (mta.y - mba.y);
    qa.z = mba.z + d1a * (mta.z - mba.z); qa.w = mba.w + d1a * (mta.w - mba.w);
    qb.x = mbb.x + d1b * (mtb.x - mbb.x); qb.y = mbb.y + d1b * (mtb.y - mbb.y);
    qb.z = mbb.z + d1b * (mtb.z - mbb.z); qb.w = mbb.w + d1b * (mtb.w - mbb.w);

    if (j < 2) {
        stg_cs4(out + ((size_t)pbase * CCH) + j * 4, qa);
        if (pbase + 1 < n)
            stg_cs4(out + ((size_t)(pbase + 1) * CCH) + j * 4, qb);
    }
}

extern "C" void kernel_launch(void* const* d_in, const int* in_sizes, int n_in,
                              void* d_out, int out_size)
{
    const float* coords = (const float*)d_in[0];
    const float* vis    = (const float*)d_in[1];
    float* out          = (float*)d_out;

    int n = in_sizes[0] / 2;   // number of points

    if (n <= NMAX) {
        int nblocks = (n + 255) / 256;
        scatter_kernel<<<nblocks, 256>>>(coords, n);
        process_kernel<<<nblocks, 256>>>(vis, out, 0);
        process_kernel<<<nblocks, 256>>>(vis, out, 1);
    } else {
        int ppb = (256 / 32) * 8 * 2;
        int blocks = (n + ppb - 1) / ppb;
        idx2pixel_r4_kernel<<<blocks, 256>>>(coords, vis, out, n);
    }
}

// round 11
// speedup vs baseline: 1.6846x; 1.4990x over previous
#include <cuda_runtime.h>

// Idx2PixelLayer bilinear gather — R4 winner structure (4 lanes/point,
// 2 points/lane-group, 4 gather LDG.128 in flight) with write-through output
// stores (st.global.wt) to eliminate L2 write-allocate fill reads on the
// 32MB output stream (output is never re-read).

#define HW 2048
#define CCH 8

__device__ __forceinline__ float4 ldg_stream4(const float* p) {
    float4 v;
    asm volatile("ld.global.cs.v4.f32 {%0,%1,%2,%3}, [%4];"
                 : "=f"(v.x), "=f"(v.y), "=f"(v.z), "=f"(v.w) : "l"(p));
    return v;
}

__device__ __forceinline__ void stg_wt4(float* p, float4 v) {
    asm volatile("st.global.wt.v4.f32 [%0], {%1,%2,%3,%4};"
                 :: "l"(p), "f"(v.x), "f"(v.y), "f"(v.z), "f"(v.w) : "memory");
}

__global__ __launch_bounds__(256) void idx2pixel_wt_kernel(
    const float* __restrict__ coords,
    const float* __restrict__ vis,
    float* __restrict__ out,
    int n)
{
    int gtid  = blockIdx.x * blockDim.x + threadIdx.x;
    int w     = gtid >> 5;            // global warp id
    int lane  = threadIdx.x & 31;
    int group = lane >> 2;            // 0..7
    int j     = lane & 3;             // 0..3 within group
    int pbase = (w * 8 + group) * 2;  // first of the point pair
    if (pbase >= n) return;

    unsigned mask = __activemask();
    const float M = (float)(HW - 4);   // 2044

    // Two points' coords in one 16B load: (x0, y0, x1, y1)
    float4 cxy = ldg_stream4(coords + (size_t)pbase * 2);

    float c0a = fmodf(cxy.x - 1.0f, M); if (c0a < 0.0f) c0a += M; c0a += 1.0f;
    float c1a = fmodf(cxy.y - 1.0f, M); if (c1a < 0.0f) c1a += M; c1a += 1.0f;
    float c0b = fmodf(cxy.z - 1.0f, M); if (c0b < 0.0f) c0b += M; c0b += 1.0f;
    float c1b = fmodf(cxy.w - 1.0f, M); if (c1b < 0.0f) c1b += M; c1b += 1.0f;

    float f0a = floorf(c0a), f1a = floorf(c1a);
    float f0b = floorf(c0b), f1b = floorf(c1b);
    float d0a = c0a - f0a, d1a = c1a - f1a;
    float d0b = c0b - f0b, d1b = c1b - f1b;
    int i0a = (int)f0a, i1a = (int)f1a;
    int i0b = (int)f0b, i1b = (int)f1b;

    const float* pa0 = vis + ((size_t)i0a * HW + i1a) * CCH + j * 4;
    const float* pa1 = pa0 + (size_t)HW * CCH;
    const float* pb0 = vis + ((size_t)i0b * HW + i1b) * CCH + j * 4;
    const float* pb1 = pb0 + (size_t)HW * CCH;

    // ---- 4 gather loads in flight ----
    float4 Aa = __ldg(reinterpret_cast<const float4*>(pa0));  // a: tl/bl half
    float4 Ba = __ldg(reinterpret_cast<const float4*>(pa1));  // a: tr/br half
    float4 Ab = __ldg(reinterpret_cast<const float4*>(pb0));
    float4 Bb = __ldg(reinterpret_cast<const float4*>(pb1));

    // v = B + d0*(A-B): lanes 0,1 -> mt ; lanes 2,3 -> mb
    float4 va, vb;
    va.x = Ba.x + d0a * (Aa.x - Ba.x);
    va.y = Ba.y + d0a * (Aa.y - Ba.y);
    va.z = Ba.z + d0a * (Aa.z - Ba.z);
    va.w = Ba.w + d0a * (Aa.w - Ba.w);
    vb.x = Bb.x + d0b * (Ab.x - Bb.x);
    vb.y = Bb.y + d0b * (Ab.y - Bb.y);
    vb.z = Bb.z + d0b * (Ab.z - Bb.z);
    vb.w = Bb.w + d0b * (Ab.w - Bb.w);

    // exchange mt <-> mb between lane pairs (xor 2)
    float4 oa, ob;
    oa.x = __shfl_xor_sync(mask, va.x, 2);
    oa.y = __shfl_xor_sync(mask, va.y, 2);
    oa.z = __shfl_xor_sync(mask, va.z, 2);
    oa.w = __shfl_xor_sync(mask, va.w, 2);
    ob.x = __shfl_xor_sync(mask, vb.x, 2);
    ob.y = __shfl_xor_sync(mask, vb.y, 2);
    ob.z = __shfl_xor_sync(mask, vb.z, 2);
    ob.w = __shfl_xor_sync(mask, vb.w, 2);

    float4 mta, mba, mtb, mbb;
    if (j < 2) { mta = va; mba = oa; mtb = vb; mbb = ob; }
    else       { mta = oa; mba = va; mtb = ob; mbb = vb; }

    float4 ra, rb;
    ra.x = mba.x + d1a * (mta.x - mba.x);
    ra.y = mba.y + d1a * (mta.y - mba.y);
    ra.z = mba.z + d1a * (mta.z - mba.z);
    ra.w = mba.w + d1a * (mta.w - mba.w);
    rb.x = mbb.x + d1b * (mtb.x - mbb.x);
    rb.y = mbb.y + d1b * (mtb.y - mbb.y);
    rb.z = mbb.z + d1b * (mtb.z - mbb.z);
    rb.w = mbb.w + d1b * (mtb.w - mbb.w);

    // off = c > 2048 never true (c in [1, 2045)): no zeroing.
    if (j < 2) {
        stg_wt4(out + ((size_t)pbase * CCH) + j * 4, ra);
        if (pbase + 1 < n)
            stg_wt4(out + ((size_t)(pbase + 1) * CCH) + j * 4, rb);
    }
}

extern "C" void kernel_launch(void* const* d_in, const int* in_sizes, int n_in,
                              void* d_out, int out_size)
{
    const float* coords = (const float*)d_in[0];
    const float* vis    = (const float*)d_in[1];
    float* out          = (float*)d_out;

    int n = in_sizes[0] / 2;             // number of points
    int threads = 256;                    // 8 warps -> 128 points/block
    int ppb = (threads / 32) * 8 * 2;
    int blocks = (n + ppb - 1) / ppb;
    idx2pixel_wt_kernel<<<blocks, threads>>>(coords, vis, out, n);
}